// round 12
// baseline (speedup 1.0000x reference)
#include <cuda_runtime.h>
#include <cuda_bf16.h>
#include <cstdint>

// ---------------------------------------------------------------- constants
#define BH        32
#define NROW      2048
#define TROW      2048
#define ROWS      (BH * 2048)        // 65536 rows per side
#define NBLK64    (ROWS / 64)        // 1024 blocks of 64 rows
#define NBLK128   (ROWS / 128)       // 512 blocks of 128 rows
#define ABLOCK    81920              // 64KB tf32 frags + 16KB bf16 frags
#define BF16_OFF  65536

// Packed operand buffers in MMA-fragment order (~40MB each)
__device__ __align__(128) unsigned char g_Apk[(size_t)NBLK128 * ABLOCK];
__device__ __align__(128) unsigned char g_Bpk[(size_t)NBLK128 * ABLOCK];
// G tf32 hi/lo in projection-B-fragment order: [kf 0..15][jj 0..7][lane] uint2
__device__ __align__(128) uint2 g_GFhi[4096];
__device__ __align__(128) uint2 g_GFlo[4096];

// ---------------------------------------------------------------- helpers
__device__ __forceinline__ uint32_t smem_u32(const void* p) {
    uint32_t a;
    asm("{ .reg .u64 t; cvta.to.shared.u64 t, %1; cvt.u32.u64 %0, t; }" : "=r"(a) : "l"(p));
    return a;
}
__device__ __forceinline__ uint32_t f2tf32(float v) {
    uint32_t o;
    asm("cvt.rna.tf32.f32 %0, %1;" : "=r"(o) : "f"(v));
    return o;
}
__device__ __forceinline__ uint32_t pack_bf16x2(float lo, float hi) {
    uint32_t o;   // first PTX source -> upper half
    asm("cvt.rn.bf16x2.f32 %0, %1, %2;" : "=r"(o) : "f"(hi), "f"(lo));
    return o;
}
__device__ __forceinline__ void cp_async16(uint32_t saddr, const void* gptr) {
    asm volatile("cp.async.cg.shared.global [%0], [%1], 16;"
                 :: "r"(saddr), "l"(__cvta_generic_to_global(gptr)) : "memory");
}
__device__ __forceinline__ float signf(float v) {
    return (v > 0.f) ? 1.f : ((v < 0.f) ? -1.f : 0.f);
}
__device__ __forceinline__ void mma_tf32_rr(float acc[4], const uint32_t a[4],
                                            uint32_t b0, uint32_t b1) {
    asm volatile("mma.sync.aligned.m16n8k8.row.col.f32.tf32.tf32.f32 "
        "{%0,%1,%2,%3}, {%4,%5,%6,%7}, {%8,%9}, {%0,%1,%2,%3};"
        : "+f"(acc[0]), "+f"(acc[1]), "+f"(acc[2]), "+f"(acc[3])
        : "r"(a[0]), "r"(a[1]), "r"(a[2]), "r"(a[3]), "r"(b0), "r"(b1));
}

// ---------------------------------------------------------------- G split
__global__ void gsplit_kernel(const float* __restrict__ G) {
    const int idx = blockIdx.x * 256 + threadIdx.x;   // 0..4095
    if (idx >= 4096) return;
    const int lane = idx & 31, jj = (idx >> 5) & 7, kf = idx >> 8;
    const int g = lane >> 2, tg = lane & 3;
    const int r = jj * 8 + g, k = kf * 8 + tg;
    const float g0 = G[k * 64 + r], g1 = G[(k + 4) * 64 + r];
    const uint32_t h0 = f2tf32(g0), h1 = f2tf32(g1);
    g_GFhi[idx] = make_uint2(h0, h1);
    g_GFlo[idx] = make_uint2(f2tf32(g0 - __uint_as_float(h0)),
                             f2tf32(g1 - __uint_as_float(h1)));
}

// ---------------------------------------------------------------- prep A (q)
#define RSTR 132
#define SMEM_PA (64 * RSTR * 4)

__global__ void __launch_bounds__(256) prep_a(const float4* __restrict__ q4) {
    extern __shared__ float sm[];
    float* Q = sm;                  // [64][RSTR]

    const int tid = threadIdx.x;
    const int blk = blockIdx.x;
    const int half = blk & 1, blk128 = blk >> 1;
    const size_t b4 = (size_t)blk * 64 * 32;

    for (int i = tid; i < 2048; i += 256) {
        const int r = i >> 5, c = i & 31;
        *(float4*)&Q[r * RSTR + c * 4] = q4[b4 + i];
    }
    __syncthreads();

    const int lane = tid & 31, w = tid >> 5;
    const int g = lane >> 2, tg = lane & 3;
    const int mt = w & 3, nh = w >> 2;
    unsigned char* Ab = g_Apk + (size_t)blk128 * ABLOCK;

    float acc[4][4];
#pragma unroll
    for (int j = 0; j < 4; j++)
#pragma unroll
        for (int c = 0; c < 4; c++) acc[j][c] = 0.f;

    const int r0 = mt * 16 + g;
#pragma unroll
    for (int kf = 0; kf < 16; kf++) {
        const int k0 = kf * 8 + tg;
        uint32_t a[4];
        a[0] = f2tf32(Q[r0 * RSTR + k0]);
        a[1] = f2tf32(Q[(r0 + 8) * RSTR + k0]);
        a[2] = f2tf32(Q[r0 * RSTR + k0 + 4]);
        a[3] = f2tf32(Q[(r0 + 8) * RSTR + k0 + 4]);
        if ((kf >> 3) == nh) {      // fused tf32 A-frag store
            uint4 v; v.x = a[0]; v.y = a[1]; v.z = a[2]; v.w = a[3];
            *(uint4*)(Ab + (size_t)((kf * 8 + half * 4 + mt) * 512 + lane * 16)) = v;
        }
#pragma unroll
        for (int j = 0; j < 4; j++) {
            const uint2 bh = __ldg(&g_GFhi[(kf * 8 + nh * 4 + j) * 32 + lane]);
            mma_tf32_rr(acc[j], a, bh.x, bh.y);
        }
    }

#pragma unroll
    for (int j = 0; j < 4; j++)
#pragma unroll
        for (int c = 0; c < 4; c++) acc[j][c] *= (1.0f / 64.0f);
#pragma unroll
    for (int kk = 0; kk < 2; kk++) {
        const int kfg = 2 * nh + kk, j0 = 2 * kk;
        uint4 v;
        v.x = pack_bf16x2(acc[j0][0],     acc[j0][1]);
        v.y = pack_bf16x2(acc[j0][2],     acc[j0][3]);
        v.z = pack_bf16x2(acc[j0 + 1][0], acc[j0 + 1][1]);
        v.w = pack_bf16x2(acc[j0 + 1][2], acc[j0 + 1][3]);
        *(uint4*)(Ab + (size_t)(BF16_OFF + (kfg * 8 + half * 4 + mt) * 512 + lane * 16)) = v;
    }
}

// ---------------------------------------------------------------- prep B (k)
#define SMEM_PB (2 * 64 * RSTR * 4)

__global__ void __launch_bounds__(256) prep_b(const float4* __restrict__ ko4,
                                              const float4* __restrict__ kq4) {
    extern __shared__ float sm[];
    float* R = sm;                      // [64][RSTR]  kq
    float* E = sm + 64 * RSTR;          // [64][RSTR]  residual

    const int tid = threadIdx.x;
    const int blk = blockIdx.x;
    const int half = blk & 1, blk128 = blk >> 1;
    const size_t b4 = (size_t)blk * 64 * 32;

    for (int i = tid; i < 2048; i += 256) {
        const int r = i >> 5, c = i & 31;
        const float4 b = kq4[b4 + i];
        const float4 a = ko4[b4 + i];
        *(float4*)&R[r * RSTR + c * 4] = b;
        *(float4*)&E[r * RSTR + c * 4] =
            make_float4(a.x - b.x, a.y - b.y, a.z - b.z, a.w - b.w);
    }
    __syncthreads();

    const int lane = tid & 31, w = tid >> 5;
    const int g = lane >> 2, tg = lane & 3;
    const int mt = w & 3, nh = w >> 2;
    unsigned char* Bb = g_Bpk + (size_t)blk128 * ABLOCK;

    // tf32 B frag-pairs from kq
#pragma unroll
    for (int kk = 0; kk < 8; kk++) {
        const int kf = nh * 8 + kk;
        const int k0 = kf * 8 + tg;
        const int n0 = mt * 16 + g;
        uint4 v;
        v.x = f2tf32(R[n0 * RSTR + k0]);
        v.y = f2tf32(R[n0 * RSTR + k0 + 4]);
        v.z = f2tf32(R[(n0 + 8) * RSTR + k0]);
        v.w = f2tf32(R[(n0 + 8) * RSTR + k0 + 4]);
        *(uint4*)(Bb + (size_t)(((kf * 8 + half * 4 + mt) * 32 + lane) * 16)) = v;
    }

    // 3xTF32 projection MMA (sign path needs precision)
    float acc[4][4];
#pragma unroll
    for (int j = 0; j < 4; j++)
#pragma unroll
        for (int c = 0; c < 4; c++) acc[j][c] = 0.f;

    const int r0 = mt * 16 + g;
#pragma unroll
    for (int kf = 0; kf < 16; kf++) {
        const int k0 = kf * 8 + tg;
        const float e0 = E[r0 * RSTR + k0];
        const float e1 = E[(r0 + 8) * RSTR + k0];
        const float e2 = E[r0 * RSTR + k0 + 4];
        const float e3 = E[(r0 + 8) * RSTR + k0 + 4];
        uint32_t ahi[4] = {f2tf32(e0), f2tf32(e1), f2tf32(e2), f2tf32(e3)};
        uint32_t alo[4];
        alo[0] = f2tf32(e0 - __uint_as_float(ahi[0]));
        alo[1] = f2tf32(e1 - __uint_as_float(ahi[1]));
        alo[2] = f2tf32(e2 - __uint_as_float(ahi[2]));
        alo[3] = f2tf32(e3 - __uint_as_float(ahi[3]));
#pragma unroll
        for (int j = 0; j < 4; j++) {
            const int gi = (kf * 8 + nh * 4 + j) * 32 + lane;
            const uint2 bh = __ldg(&g_GFhi[gi]);
            const uint2 bl = __ldg(&g_GFlo[gi]);
            mma_tf32_rr(acc[j], ahi, bh.x, bh.y);
            mma_tf32_rr(acc[j], ahi, bl.x, bl.y);
            mma_tf32_rr(acc[j], alo, bh.x, bh.y);
        }
    }

#pragma unroll
    for (int j = 0; j < 4; j++)
#pragma unroll
        for (int c = 0; c < 4; c++) acc[j][c] = signf(acc[j][c]);
#pragma unroll
    for (int kk = 0; kk < 2; kk++) {
        const int kfg = 2 * nh + kk, j0 = 2 * kk;
        uint4 v;
        v.x = pack_bf16x2(acc[j0][0],     acc[j0][1]);
        v.y = pack_bf16x2(acc[j0 + 1][0], acc[j0 + 1][1]);
        v.z = pack_bf16x2(acc[j0][2],     acc[j0][3]);
        v.w = pack_bf16x2(acc[j0 + 1][2], acc[j0 + 1][3]);
        *(uint4*)(Bb + (size_t)(BF16_OFF + ((kfg * 8 + half * 4 + mt) * 32 + lane) * 16)) = v;
    }
}

// ---------------------------------------------------------------- GEMM
// 128x256 CTA tile, 8 warps (2m x 4n), 64x64 warp tile, 1 CTA/SM.
// 5 K-stages; stage = A 16KB + B(two 128-col blocks) 32KB = 48KB; ring of 3.
// LDS: 8x LDS.128 per warp per kf for 32 MMAs (128 B/MMA, was 192).
#define STAGE_BYTES 49152
#define SMEM_GEMM   (3 * STAGE_BYTES)

template <bool TF32>
__device__ __forceinline__ void compute_stage(uint32_t sA, uint32_t sB,
                                              int mw, int nw, int lane,
                                              float acc[4][8][4]) {
#pragma unroll
    for (int kf = 0; kf < 4; kf++) {
        uint32_t b[8][2];
#pragma unroll
        for (int jp = 0; jp < 4; jp++) {
            const int p256 = nw * 4 + jp;               // 0..15
            const int half = p256 >> 3, pw = p256 & 7;
            uint32_t addr = sB + half * 16384 + ((kf * 8 + pw) * 32 + lane) * 16;
            asm volatile("ld.shared.v4.u32 {%0,%1,%2,%3}, [%4];"
                : "=r"(b[2 * jp][0]), "=r"(b[2 * jp][1]),
                  "=r"(b[2 * jp + 1][0]), "=r"(b[2 * jp + 1][1])
                : "r"(addr) : "memory");
        }
#pragma unroll
        for (int i = 0; i < 4; i++) {
            uint32_t a[4];
            uint32_t addr = sA + ((kf * 8 + mw * 4 + i) * 32 + lane) * 16;
            asm volatile("ld.shared.v4.u32 {%0,%1,%2,%3}, [%4];"
                : "=r"(a[0]), "=r"(a[1]), "=r"(a[2]), "=r"(a[3]) : "r"(addr) : "memory");
#pragma unroll
            for (int j = 0; j < 8; j++) {
                if (TF32)
                    asm volatile("mma.sync.aligned.m16n8k8.row.col.f32.tf32.tf32.f32 "
                        "{%0,%1,%2,%3}, {%4,%5,%6,%7}, {%8,%9}, {%0,%1,%2,%3};"
                        : "+f"(acc[i][j][0]), "+f"(acc[i][j][1]),
                          "+f"(acc[i][j][2]), "+f"(acc[i][j][3])
                        : "r"(a[0]), "r"(a[1]), "r"(a[2]), "r"(a[3]),
                          "r"(b[j][0]), "r"(b[j][1]));
                else
                    asm volatile("mma.sync.aligned.m16n8k16.row.col.f32.bf16.bf16.f32 "
                        "{%0,%1,%2,%3}, {%4,%5,%6,%7}, {%8,%9}, {%0,%1,%2,%3};"
                        : "+f"(acc[i][j][0]), "+f"(acc[i][j][1]),
                          "+f"(acc[i][j][2]), "+f"(acc[i][j][3])
                        : "r"(a[0]), "r"(a[1]), "r"(a[2]), "r"(a[3]),
                          "r"(b[j][0]), "r"(b[j][1]));
            }
        }
    }
}

__global__ void __launch_bounds__(256, 1) gemm_kernel(float* __restrict__ out) {
    extern __shared__ char smem[];
    const uint32_t sb = smem_u32(smem);
    const int tid  = threadIdx.x;
    const int lane = tid & 31;
    const int w    = tid >> 5;
    const int mw   = w & 1;      // 2 m-warps x 64 rows
    const int nw   = w >> 1;     // 4 n-warps x 64 cols

    const int bx = blockIdx.x, by = blockIdx.y, h = blockIdx.z;
    const unsigned char* Ab  = g_Apk + (size_t)(h * 16 + by) * ABLOCK;
    const unsigned char* Bb0 = g_Bpk + (size_t)(h * 16 + bx * 2) * ABLOCK;
    const unsigned char* Bb1 = Bb0 + ABLOCK;

    auto prefetch = [&](int s) {
        const int sl = s % 3;
        const size_t goff = (s < 4) ? (size_t)s * 16384 : (size_t)BF16_OFF;
        const uint32_t dA  = sb + sl * STAGE_BYTES;
        const uint32_t dB0 = dA + 16384;
        const uint32_t dB1 = dA + 32768;
#pragma unroll
        for (int i = 0; i < 4; i++) {
            const int off = (tid + i * 256) * 16;
            cp_async16(dA  + off, Ab  + goff + off);
            cp_async16(dB0 + off, Bb0 + goff + off);
            cp_async16(dB1 + off, Bb1 + goff + off);
        }
        asm volatile("cp.async.commit_group;" ::: "memory");
    };

    float acc[4][8][4];
#pragma unroll
    for (int i = 0; i < 4; i++)
#pragma unroll
        for (int j = 0; j < 8; j++)
#pragma unroll
            for (int c = 0; c < 4; c++) acc[i][j][c] = 0.f;

    prefetch(0);
    prefetch(1);

#pragma unroll
    for (int s = 0; s < 5; s++) {
        if (s == 4) asm volatile("cp.async.wait_group 0;" ::: "memory");
        else        asm volatile("cp.async.wait_group 1;" ::: "memory");
        __syncthreads();
        const int sl = s % 3;
        const uint32_t sA = sb + sl * STAGE_BYTES;
        const uint32_t sB = sA + 16384;
        if (s < 4) compute_stage<true >(sA, sB, mw, nw, lane, acc);
        else       compute_stage<false>(sA, sB, mw, nw, lane, acc);
        __syncthreads();
        if (s + 2 < 5) prefetch(s + 2);
    }

    // epilogue: STG.64, coalesced rows
    const int g = lane >> 2, tg = lane & 3;
    const size_t rowbase = (size_t)h * 2048;
#pragma unroll
    for (int i = 0; i < 4; i++) {
        const int m = by * 128 + mw * 64 + i * 16 + g;
        float* r0 = out + (rowbase + m)     * 2048 + bx * 256 + nw * 64;
        float* r1 = out + (rowbase + m + 8) * 2048 + bx * 256 + nw * 64;
#pragma unroll
        for (int j = 0; j < 8; j++) {
            *(float2*)(r0 + j * 8 + tg * 2) = make_float2(acc[i][j][0], acc[i][j][1]);
            *(float2*)(r1 + j * 8 + tg * 2) = make_float2(acc[i][j][2], acc[i][j][3]);
        }
    }
}

// ---------------------------------------------------------------- launch
extern "C" void kernel_launch(void* const* d_in, const int* in_sizes, int n_in,
                              void* d_out, int out_size) {
    const float* q  = (const float*)d_in[0];
    const float* ko = (const float*)d_in[1];
    const float* kq = (const float*)d_in[2];
    const float* G  = (const float*)d_in[3];
    float* out = (float*)d_out;

    cudaFuncSetAttribute(prep_a, cudaFuncAttributeMaxDynamicSharedMemorySize, SMEM_PA);
    cudaFuncSetAttribute(prep_b, cudaFuncAttributeMaxDynamicSharedMemorySize, SMEM_PB);
    cudaFuncSetAttribute(gemm_kernel, cudaFuncAttributeMaxDynamicSharedMemorySize, SMEM_GEMM);

    gsplit_kernel<<<16, 256>>>(G);
    prep_a<<<NBLK64, 256, SMEM_PA>>>((const float4*)q);
    prep_b<<<NBLK64, 256, SMEM_PB>>>((const float4*)ko, (const float4*)kq);

    dim3 grid(TROW / 256, NROW / 128, BH);
    gemm_kernel<<<grid, 256, SMEM_GEMM>>>(out);
}

// round 14
// speedup vs baseline: 1.1328x; 1.1328x over previous
#include <cuda_runtime.h>
#include <cuda_bf16.h>
#include <cstdint>

// ---------------------------------------------------------------- constants
#define BH        32
#define NROW      2048
#define TROW      2048
#define ROWS      (BH * 2048)        // 65536 rows per side
#define NBLK64    (ROWS / 64)        // 1024 blocks of 64 rows
#define NBLK128   (ROWS / 128)       // 512 blocks of 128 rows
#define ABLOCK    81920              // 64KB tf32 frags + 16KB bf16 frags
#define BF16_OFF  65536

// Packed operand buffers in MMA-fragment order (~40MB each)
__device__ __align__(128) unsigned char g_Apk[(size_t)NBLK128 * ABLOCK];
__device__ __align__(128) unsigned char g_Bpk[(size_t)NBLK128 * ABLOCK];
// G tf32 hi/lo in projection-B-fragment order: [kf 0..15][jj 0..7][lane] uint2
__device__ __align__(128) uint2 g_GFhi[4096];
__device__ __align__(128) uint2 g_GFlo[4096];

// ---------------------------------------------------------------- helpers
__device__ __forceinline__ uint32_t smem_u32(const void* p) {
    uint32_t a;
    asm("{ .reg .u64 t; cvta.to.shared.u64 t, %1; cvt.u32.u64 %0, t; }" : "=r"(a) : "l"(p));
    return a;
}
__device__ __forceinline__ uint32_t f2tf32(float v) {
    uint32_t o;
    asm("cvt.rna.tf32.f32 %0, %1;" : "=r"(o) : "f"(v));
    return o;
}
__device__ __forceinline__ uint32_t pack_bf16x2(float lo, float hi) {
    uint32_t o;   // first PTX source -> upper half
    asm("cvt.rn.bf16x2.f32 %0, %1, %2;" : "=r"(o) : "f"(hi), "f"(lo));
    return o;
}
__device__ __forceinline__ void cp_async16(uint32_t saddr, const void* gptr) {
    asm volatile("cp.async.cg.shared.global [%0], [%1], 16;"
                 :: "r"(saddr), "l"(__cvta_generic_to_global(gptr)) : "memory");
}
__device__ __forceinline__ float signf(float v) {
    return (v > 0.f) ? 1.f : ((v < 0.f) ? -1.f : 0.f);
}
__device__ __forceinline__ void mma_tf32_rr(float acc[4], const uint32_t a[4],
                                            uint32_t b0, uint32_t b1) {
    asm volatile("mma.sync.aligned.m16n8k8.row.col.f32.tf32.tf32.f32 "
        "{%0,%1,%2,%3}, {%4,%5,%6,%7}, {%8,%9}, {%0,%1,%2,%3};"
        : "+f"(acc[0]), "+f"(acc[1]), "+f"(acc[2]), "+f"(acc[3])
        : "r"(a[0]), "r"(a[1]), "r"(a[2]), "r"(a[3]), "r"(b0), "r"(b1));
}

// ---------------------------------------------------------------- G split
__global__ void gsplit_kernel(const float* __restrict__ G) {
    const int idx = blockIdx.x * 256 + threadIdx.x;   // 0..4095
    if (idx >= 4096) return;
    const int lane = idx & 31, jj = (idx >> 5) & 7, kf = idx >> 8;
    const int g = lane >> 2, tg = lane & 3;
    const int r = jj * 8 + g, k = kf * 8 + tg;
    const float g0 = G[k * 64 + r], g1 = G[(k + 4) * 64 + r];
    const uint32_t h0 = f2tf32(g0), h1 = f2tf32(g1);
    g_GFhi[idx] = make_uint2(h0, h1);
    g_GFlo[idx] = make_uint2(f2tf32(g0 - __uint_as_float(h0)),
                             f2tf32(g1 - __uint_as_float(h1)));
}

// ---------------------------------------------------------------- prep A (q)
#define RSTR 132
#define SMEM_PA (64 * RSTR * 4)

__global__ void __launch_bounds__(256) prep_a(const float4* __restrict__ q4) {
    extern __shared__ float sm[];
    float* Q = sm;                  // [64][RSTR]

    const int tid = threadIdx.x;
    const int blk = blockIdx.x;
    const int half = blk & 1, blk128 = blk >> 1;
    const size_t b4 = (size_t)blk * 64 * 32;

    for (int i = tid; i < 2048; i += 256) {
        const int r = i >> 5, c = i & 31;
        *(float4*)&Q[r * RSTR + c * 4] = q4[b4 + i];
    }
    __syncthreads();

    const int lane = tid & 31, w = tid >> 5;
    const int g = lane >> 2, tg = lane & 3;
    const int mt = w & 3, nh = w >> 2;
    unsigned char* Ab = g_Apk + (size_t)blk128 * ABLOCK;

    float acc[4][4];
#pragma unroll
    for (int j = 0; j < 4; j++)
#pragma unroll
        for (int c = 0; c < 4; c++) acc[j][c] = 0.f;

    const int r0 = mt * 16 + g;
#pragma unroll
    for (int kf = 0; kf < 16; kf++) {
        const int k0 = kf * 8 + tg;
        uint32_t a[4];
        a[0] = f2tf32(Q[r0 * RSTR + k0]);
        a[1] = f2tf32(Q[(r0 + 8) * RSTR + k0]);
        a[2] = f2tf32(Q[r0 * RSTR + k0 + 4]);
        a[3] = f2tf32(Q[(r0 + 8) * RSTR + k0 + 4]);
        if ((kf >> 3) == nh) {      // fused tf32 A-frag store
            uint4 v; v.x = a[0]; v.y = a[1]; v.z = a[2]; v.w = a[3];
            *(uint4*)(Ab + (size_t)((kf * 8 + half * 4 + mt) * 512 + lane * 16)) = v;
        }
#pragma unroll
        for (int j = 0; j < 4; j++) {
            const uint2 bh = __ldg(&g_GFhi[(kf * 8 + nh * 4 + j) * 32 + lane]);
            mma_tf32_rr(acc[j], a, bh.x, bh.y);
        }
    }

#pragma unroll
    for (int j = 0; j < 4; j++)
#pragma unroll
        for (int c = 0; c < 4; c++) acc[j][c] *= (1.0f / 64.0f);
#pragma unroll
    for (int kk = 0; kk < 2; kk++) {
        const int kfg = 2 * nh + kk, j0 = 2 * kk;
        uint4 v;
        v.x = pack_bf16x2(acc[j0][0],     acc[j0][1]);
        v.y = pack_bf16x2(acc[j0][2],     acc[j0][3]);
        v.z = pack_bf16x2(acc[j0 + 1][0], acc[j0 + 1][1]);
        v.w = pack_bf16x2(acc[j0 + 1][2], acc[j0 + 1][3]);
        *(uint4*)(Ab + (size_t)(BF16_OFF + (kfg * 8 + half * 4 + mt) * 512 + lane * 16)) = v;
    }
}

// ---------------------------------------------------------------- prep B (k)
#define SMEM_PB (2 * 64 * RSTR * 4)

__global__ void __launch_bounds__(256) prep_b(const float4* __restrict__ ko4,
                                              const float4* __restrict__ kq4) {
    extern __shared__ float sm[];
    float* R = sm;                      // [64][RSTR]  kq
    float* E = sm + 64 * RSTR;          // [64][RSTR]  residual

    const int tid = threadIdx.x;
    const int blk = blockIdx.x;
    const int half = blk & 1, blk128 = blk >> 1;
    const size_t b4 = (size_t)blk * 64 * 32;

    for (int i = tid; i < 2048; i += 256) {
        const int r = i >> 5, c = i & 31;
        const float4 b = kq4[b4 + i];
        const float4 a = ko4[b4 + i];
        *(float4*)&R[r * RSTR + c * 4] = b;
        *(float4*)&E[r * RSTR + c * 4] =
            make_float4(a.x - b.x, a.y - b.y, a.z - b.z, a.w - b.w);
    }
    __syncthreads();

    const int lane = tid & 31, w = tid >> 5;
    const int g = lane >> 2, tg = lane & 3;
    const int mt = w & 3, nh = w >> 2;
    unsigned char* Bb = g_Bpk + (size_t)blk128 * ABLOCK;

    // tf32 B frag-pairs from kq
#pragma unroll
    for (int kk = 0; kk < 8; kk++) {
        const int kf = nh * 8 + kk;
        const int k0 = kf * 8 + tg;
        const int n0 = mt * 16 + g;
        uint4 v;
        v.x = f2tf32(R[n0 * RSTR + k0]);
        v.y = f2tf32(R[n0 * RSTR + k0 + 4]);
        v.z = f2tf32(R[(n0 + 8) * RSTR + k0]);
        v.w = f2tf32(R[(n0 + 8) * RSTR + k0 + 4]);
        *(uint4*)(Bb + (size_t)(((kf * 8 + half * 4 + mt) * 32 + lane) * 16)) = v;
    }

    // 3xTF32 projection MMA (sign path needs precision)
    float acc[4][4];
#pragma unroll
    for (int j = 0; j < 4; j++)
#pragma unroll
        for (int c = 0; c < 4; c++) acc[j][c] = 0.f;

    const int r0 = mt * 16 + g;
#pragma unroll
    for (int kf = 0; kf < 16; kf++) {
        const int k0 = kf * 8 + tg;
        const float e0 = E[r0 * RSTR + k0];
        const float e1 = E[(r0 + 8) * RSTR + k0];
        const float e2 = E[r0 * RSTR + k0 + 4];
        const float e3 = E[(r0 + 8) * RSTR + k0 + 4];
        uint32_t ahi[4] = {f2tf32(e0), f2tf32(e1), f2tf32(e2), f2tf32(e3)};
        uint32_t alo[4];
        alo[0] = f2tf32(e0 - __uint_as_float(ahi[0]));
        alo[1] = f2tf32(e1 - __uint_as_float(ahi[1]));
        alo[2] = f2tf32(e2 - __uint_as_float(ahi[2]));
        alo[3] = f2tf32(e3 - __uint_as_float(ahi[3]));
#pragma unroll
        for (int j = 0; j < 4; j++) {
            const int gi = (kf * 8 + nh * 4 + j) * 32 + lane;
            const uint2 bh = __ldg(&g_GFhi[gi]);
            const uint2 bl = __ldg(&g_GFlo[gi]);
            mma_tf32_rr(acc[j], ahi, bh.x, bh.y);
            mma_tf32_rr(acc[j], ahi, bl.x, bl.y);
            mma_tf32_rr(acc[j], alo, bh.x, bh.y);
        }
    }

#pragma unroll
    for (int j = 0; j < 4; j++)
#pragma unroll
        for (int c = 0; c < 4; c++) acc[j][c] = signf(acc[j][c]);
#pragma unroll
    for (int kk = 0; kk < 2; kk++) {
        const int kfg = 2 * nh + kk, j0 = 2 * kk;
        uint4 v;
        v.x = pack_bf16x2(acc[j0][0],     acc[j0][1]);
        v.y = pack_bf16x2(acc[j0 + 1][0], acc[j0 + 1][1]);
        v.z = pack_bf16x2(acc[j0][2],     acc[j0][3]);
        v.w = pack_bf16x2(acc[j0 + 1][2], acc[j0 + 1][3]);
        *(uint4*)(Bb + (size_t)(BF16_OFF + ((kfg * 8 + half * 4 + mt) * 32 + lane) * 16)) = v;
    }
}

// ---------------------------------------------------------------- GEMM
// 128x128 tile, 8 warps (4m x 2n), 2 CTA/SM, 5 K-stages of 32KB, ring of 3.
// Mainloop: ONE barrier per stage; prefetch issued immediately after it.
#define STAGE_BYTES 32768
#define SMEM_GEMM   (3 * STAGE_BYTES)

template <bool TF32>
__device__ __forceinline__ void compute_stage(uint32_t sA, uint32_t sB,
                                              int mw, int nw, int lane,
                                              float acc[2][8][4]) {
#pragma unroll
    for (int kf = 0; kf < 4; kf++) {
        uint32_t b[8][2];
#pragma unroll
        for (int jp = 0; jp < 4; jp++) {
            uint32_t addr = sB + ((kf * 8 + nw * 4 + jp) * 32 + lane) * 16;
            asm volatile("ld.shared.v4.u32 {%0,%1,%2,%3}, [%4];"
                : "=r"(b[2 * jp][0]), "=r"(b[2 * jp][1]),
                  "=r"(b[2 * jp + 1][0]), "=r"(b[2 * jp + 1][1])
                : "r"(addr) : "memory");
        }
#pragma unroll
        for (int i = 0; i < 2; i++) {
            uint32_t a[4];
            uint32_t addr = sA + ((kf * 8 + mw * 2 + i) * 32 + lane) * 16;
            asm volatile("ld.shared.v4.u32 {%0,%1,%2,%3}, [%4];"
                : "=r"(a[0]), "=r"(a[1]), "=r"(a[2]), "=r"(a[3]) : "r"(addr) : "memory");
#pragma unroll
            for (int j = 0; j < 8; j++) {
                if (TF32)
                    asm volatile("mma.sync.aligned.m16n8k8.row.col.f32.tf32.tf32.f32 "
                        "{%0,%1,%2,%3}, {%4,%5,%6,%7}, {%8,%9}, {%0,%1,%2,%3};"
                        : "+f"(acc[i][j][0]), "+f"(acc[i][j][1]),
                          "+f"(acc[i][j][2]), "+f"(acc[i][j][3])
                        : "r"(a[0]), "r"(a[1]), "r"(a[2]), "r"(a[3]),
                          "r"(b[j][0]), "r"(b[j][1]));
                else
                    asm volatile("mma.sync.aligned.m16n8k16.row.col.f32.bf16.bf16.f32 "
                        "{%0,%1,%2,%3}, {%4,%5,%6,%7}, {%8,%9}, {%0,%1,%2,%3};"
                        : "+f"(acc[i][j][0]), "+f"(acc[i][j][1]),
                          "+f"(acc[i][j][2]), "+f"(acc[i][j][3])
                        : "r"(a[0]), "r"(a[1]), "r"(a[2]), "r"(a[3]),
                          "r"(b[j][0]), "r"(b[j][1]));
            }
        }
    }
}

__global__ void __launch_bounds__(256, 2) gemm_kernel(float* __restrict__ out) {
    extern __shared__ char smem[];
    const uint32_t sb = smem_u32(smem);
    const int tid  = threadIdx.x;
    const int lane = tid & 31;
    const int w    = tid >> 5;
    const int mw   = w & 3;
    const int nw   = w >> 2;

    const int bx = blockIdx.x, by = blockIdx.y, h = blockIdx.z;
    const unsigned char* Ab = g_Apk + (size_t)(h * 16 + by) * ABLOCK;
    const unsigned char* Bb = g_Bpk + (size_t)(h * 16 + bx) * ABLOCK;

    auto prefetch = [&](int s) {
        const int sl = s % 3;
        const size_t goff = (s < 4) ? (size_t)s * 16384 : (size_t)BF16_OFF;
        const uint32_t dA = sb + sl * STAGE_BYTES;
        const uint32_t dB = dA + 16384;
#pragma unroll
        for (int i = 0; i < 4; i++) {
            const int off = (tid + i * 256) * 16;
            cp_async16(dA + off, Ab + goff + off);
            cp_async16(dB + off, Bb + goff + off);
        }
        asm volatile("cp.async.commit_group;" ::: "memory");
    };

    float acc[2][8][4];
#pragma unroll
    for (int i = 0; i < 2; i++)
#pragma unroll
        for (int j = 0; j < 8; j++)
#pragma unroll
            for (int c = 0; c < 4; c++) acc[i][j][c] = 0.f;

    prefetch(0);
    prefetch(1);

#pragma unroll
    for (int s = 0; s < 5; s++) {
        // wait for stage s data: allow only the most recent group in flight
        if (s == 4) asm volatile("cp.async.wait_group 0;" ::: "memory");
        else        asm volatile("cp.async.wait_group 1;" ::: "memory");
        __syncthreads();   // also proves all warps finished stage s-1 reads
        if (s + 2 < 5) prefetch(s + 2);   // slot (s+2)%3 == (s-1)%3, now free
        const uint32_t sA = sb + (s % 3) * STAGE_BYTES;
        const uint32_t sB = sA + 16384;
        if (s < 4) compute_stage<true >(sA, sB, mw, nw, lane, acc);
        else       compute_stage<false>(sA, sB, mw, nw, lane, acc);
        // no trailing barrier: next stage's leading barrier provides it
    }

    // epilogue: STG.64, full coalesced rows
    const int g = lane >> 2, tg = lane & 3;
    const size_t rowbase = (size_t)h * 2048;
#pragma unroll
    for (int i = 0; i < 2; i++) {
        const int m = by * 128 + mw * 32 + i * 16 + g;
        float* r0 = out + (rowbase + m)     * 2048 + bx * 128 + nw * 64;
        float* r1 = out + (rowbase + m + 8) * 2048 + bx * 128 + nw * 64;
#pragma unroll
        for (int j = 0; j < 8; j++) {
            *(float2*)(r0 + j * 8 + tg * 2) = make_float2(acc[i][j][0], acc[i][j][1]);
            *(float2*)(r1 + j * 8 + tg * 2) = make_float2(acc[i][j][2], acc[i][j][3]);
        }
    }
}

// ---------------------------------------------------------------- launch
extern "C" void kernel_launch(void* const* d_in, const int* in_sizes, int n_in,
                              void* d_out, int out_size) {
    const float* q  = (const float*)d_in[0];
    const float* ko = (const float*)d_in[1];
    const float* kq = (const float*)d_in[2];
    const float* G  = (const float*)d_in[3];
    float* out = (float*)d_out;

    cudaFuncSetAttribute(prep_a, cudaFuncAttributeMaxDynamicSharedMemorySize, SMEM_PA);
    cudaFuncSetAttribute(prep_b, cudaFuncAttributeMaxDynamicSharedMemorySize, SMEM_PB);
    cudaFuncSetAttribute(gemm_kernel, cudaFuncAttributeMaxDynamicSharedMemorySize, SMEM_GEMM);

    gsplit_kernel<<<16, 256>>>(G);
    prep_a<<<NBLK64, 256, SMEM_PA>>>((const float4*)q);
    prep_b<<<NBLK64, 256, SMEM_PB>>>((const float4*)ko, (const float4*)kq);

    dim3 grid(TROW / 128, NROW / 128, BH);
    gemm_kernel<<<grid, 256, SMEM_GEMM>>>(out);
}

// round 16
// speedup vs baseline: 1.1499x; 1.0151x over previous
#include <cuda_runtime.h>
#include <cuda_bf16.h>
#include <cstdint>

// ---------------------------------------------------------------- constants
#define BH        32
#define NROW      2048
#define TROW      2048
#define ROWS      (BH * 2048)        // 65536 rows per side
#define NBLK64    (ROWS / 64)        // 1024 blocks of 64 rows
#define NBLK128   (ROWS / 128)       // 512 blocks of 128 rows
#define ABLOCK    81920              // 64KB tf32 frags + 16KB bf16 frags
#define BF16_OFF  65536

// Packed operand buffers in MMA-fragment order (~40MB each)
__device__ __align__(128) unsigned char g_Apk[(size_t)NBLK128 * ABLOCK];
__device__ __align__(128) unsigned char g_Bpk[(size_t)NBLK128 * ABLOCK];
// G tf32 hi/lo in projection-B-fragment order: [kf 0..15][jj 0..7][lane] uint2
__device__ __align__(128) uint2 g_GFhi[4096];
__device__ __align__(128) uint2 g_GFlo[4096];

// ---------------------------------------------------------------- helpers
__device__ __forceinline__ uint32_t smem_u32(const void* p) {
    uint32_t a;
    asm("{ .reg .u64 t; cvta.to.shared.u64 t, %1; cvt.u32.u64 %0, t; }" : "=r"(a) : "l"(p));
    return a;
}
__device__ __forceinline__ uint32_t f2tf32(float v) {
    uint32_t o;
    asm("cvt.rna.tf32.f32 %0, %1;" : "=r"(o) : "f"(v));
    return o;
}
__device__ __forceinline__ uint32_t pack_bf16x2(float lo, float hi) {
    uint32_t o;   // first PTX source -> upper half
    asm("cvt.rn.bf16x2.f32 %0, %1, %2;" : "=r"(o) : "f"(hi), "f"(lo));
    return o;
}
__device__ __forceinline__ void cp_async16(uint32_t saddr, const void* gptr) {
    asm volatile("cp.async.cg.shared.global [%0], [%1], 16;"
                 :: "r"(saddr), "l"(__cvta_generic_to_global(gptr)) : "memory");
}
__device__ __forceinline__ float signf(float v) {
    return (v > 0.f) ? 1.f : ((v < 0.f) ? -1.f : 0.f);
}
__device__ __forceinline__ void mma_tf32_rr(float acc[4], const uint32_t a[4],
                                            uint32_t b0, uint32_t b1) {
    asm volatile("mma.sync.aligned.m16n8k8.row.col.f32.tf32.tf32.f32 "
        "{%0,%1,%2,%3}, {%4,%5,%6,%7}, {%8,%9}, {%0,%1,%2,%3};"
        : "+f"(acc[0]), "+f"(acc[1]), "+f"(acc[2]), "+f"(acc[3])
        : "r"(a[0]), "r"(a[1]), "r"(a[2]), "r"(a[3]), "r"(b0), "r"(b1));
}

// ---------------------------------------------------------------- G split
__global__ void gsplit_kernel(const float* __restrict__ G) {
    const int idx = blockIdx.x * 256 + threadIdx.x;   // 0..4095
    if (idx >= 4096) return;
    const int lane = idx & 31, jj = (idx >> 5) & 7, kf = idx >> 8;
    const int g = lane >> 2, tg = lane & 3;
    const int r = jj * 8 + g, k = kf * 8 + tg;
    const float g0 = G[k * 64 + r], g1 = G[(k + 4) * 64 + r];
    const uint32_t h0 = f2tf32(g0), h1 = f2tf32(g1);
    g_GFhi[idx] = make_uint2(h0, h1);
    g_GFlo[idx] = make_uint2(f2tf32(g0 - __uint_as_float(h0)),
                             f2tf32(g1 - __uint_as_float(h1)));
}

// ---------------------------------------------------------------- prep (merged)
// blockIdx.y == 0: A side (q). blockIdx.y == 1: B side (ko, kq).
// Uniform 67.6KB smem -> 3 CTA/SM; both sides co-schedule in one grid.
#define RSTR 132
#define SMEM_PREP (2 * 64 * RSTR * 4)

__global__ void __launch_bounds__(256) prep_ab(const float4* __restrict__ q4,
                                               const float4* __restrict__ ko4,
                                               const float4* __restrict__ kq4) {
    extern __shared__ float sm[];
    float* R = sm;                      // [64][RSTR]
    float* E = sm + 64 * RSTR;          // [64][RSTR] (B side only)

    const int tid = threadIdx.x;
    const int blk = blockIdx.x;
    const int side = blockIdx.y;
    const int half = blk & 1, blk128 = blk >> 1;
    const size_t b4 = (size_t)blk * 64 * 32;

    if (side == 0) {
        for (int i = tid; i < 2048; i += 256) {
            const int r = i >> 5, c = i & 31;
            *(float4*)&R[r * RSTR + c * 4] = q4[b4 + i];
        }
    } else {
        for (int i = tid; i < 2048; i += 256) {
            const int r = i >> 5, c = i & 31;
            const float4 b = kq4[b4 + i];
            const float4 a = ko4[b4 + i];
            *(float4*)&R[r * RSTR + c * 4] = b;
            *(float4*)&E[r * RSTR + c * 4] =
                make_float4(a.x - b.x, a.y - b.y, a.z - b.z, a.w - b.w);
        }
    }
    __syncthreads();

    const int lane = tid & 31, w = tid >> 5;
    const int g = lane >> 2, tg = lane & 3;
    const int mt = w & 3, nh = w >> 2;
    const int r0 = mt * 16 + g;

    if (side == 0) {
        unsigned char* Ab = g_Apk + (size_t)blk128 * ABLOCK;

        float acc[4][4];
#pragma unroll
        for (int j = 0; j < 4; j++)
#pragma unroll
            for (int c = 0; c < 4; c++) acc[j][c] = 0.f;

#pragma unroll
        for (int kf = 0; kf < 16; kf++) {
            const int k0 = kf * 8 + tg;
            uint32_t a[4];
            a[0] = f2tf32(R[r0 * RSTR + k0]);
            a[1] = f2tf32(R[(r0 + 8) * RSTR + k0]);
            a[2] = f2tf32(R[r0 * RSTR + k0 + 4]);
            a[3] = f2tf32(R[(r0 + 8) * RSTR + k0 + 4]);
            if ((kf >> 3) == nh) {      // fused tf32 A-frag store
                uint4 v; v.x = a[0]; v.y = a[1]; v.z = a[2]; v.w = a[3];
                *(uint4*)(Ab + (size_t)((kf * 8 + half * 4 + mt) * 512 + lane * 16)) = v;
            }
#pragma unroll
            for (int j = 0; j < 4; j++) {
                const uint2 bh = __ldg(&g_GFhi[(kf * 8 + nh * 4 + j) * 32 + lane]);
                mma_tf32_rr(acc[j], a, bh.x, bh.y);
            }
        }

#pragma unroll
        for (int j = 0; j < 4; j++)
#pragma unroll
            for (int c = 0; c < 4; c++) acc[j][c] *= (1.0f / 64.0f);
#pragma unroll
        for (int kk = 0; kk < 2; kk++) {
            const int kfg = 2 * nh + kk, j0 = 2 * kk;
            uint4 v;
            v.x = pack_bf16x2(acc[j0][0],     acc[j0][1]);
            v.y = pack_bf16x2(acc[j0][2],     acc[j0][3]);
            v.z = pack_bf16x2(acc[j0 + 1][0], acc[j0 + 1][1]);
            v.w = pack_bf16x2(acc[j0 + 1][2], acc[j0 + 1][3]);
            *(uint4*)(Ab + (size_t)(BF16_OFF + (kfg * 8 + half * 4 + mt) * 512 + lane * 16)) = v;
        }
    } else {
        unsigned char* Bb = g_Bpk + (size_t)blk128 * ABLOCK;

        // tf32 B frag-pairs from kq
#pragma unroll
        for (int kk = 0; kk < 8; kk++) {
            const int kf = nh * 8 + kk;
            const int k0 = kf * 8 + tg;
            const int n0 = mt * 16 + g;
            uint4 v;
            v.x = f2tf32(R[n0 * RSTR + k0]);
            v.y = f2tf32(R[n0 * RSTR + k0 + 4]);
            v.z = f2tf32(R[(n0 + 8) * RSTR + k0]);
            v.w = f2tf32(R[(n0 + 8) * RSTR + k0 + 4]);
            *(uint4*)(Bb + (size_t)(((kf * 8 + half * 4 + mt) * 32 + lane) * 16)) = v;
        }

        // 3xTF32 projection MMA (sign path needs precision)
        float acc[4][4];
#pragma unroll
        for (int j = 0; j < 4; j++)
#pragma unroll
            for (int c = 0; c < 4; c++) acc[j][c] = 0.f;

#pragma unroll
        for (int kf = 0; kf < 16; kf++) {
            const int k0 = kf * 8 + tg;
            const float e0 = E[r0 * RSTR + k0];
            const float e1 = E[(r0 + 8) * RSTR + k0];
            const float e2 = E[r0 * RSTR + k0 + 4];
            const float e3 = E[(r0 + 8) * RSTR + k0 + 4];
            uint32_t ahi[4] = {f2tf32(e0), f2tf32(e1), f2tf32(e2), f2tf32(e3)};
            uint32_t alo[4];
            alo[0] = f2tf32(e0 - __uint_as_float(ahi[0]));
            alo[1] = f2tf32(e1 - __uint_as_float(ahi[1]));
            alo[2] = f2tf32(e2 - __uint_as_float(ahi[2]));
            alo[3] = f2tf32(e3 - __uint_as_float(ahi[3]));
#pragma unroll
            for (int j = 0; j < 4; j++) {
                const int gi = (kf * 8 + nh * 4 + j) * 32 + lane;
                const uint2 bh = __ldg(&g_GFhi[gi]);
                const uint2 bl = __ldg(&g_GFlo[gi]);
                mma_tf32_rr(acc[j], ahi, bh.x, bh.y);
                mma_tf32_rr(acc[j], ahi, bl.x, bl.y);
                mma_tf32_rr(acc[j], alo, bh.x, bh.y);
            }
        }

#pragma unroll
        for (int j = 0; j < 4; j++)
#pragma unroll
            for (int c = 0; c < 4; c++) acc[j][c] = signf(acc[j][c]);
#pragma unroll
        for (int kk = 0; kk < 2; kk++) {
            const int kfg = 2 * nh + kk, j0 = 2 * kk;
            uint4 v;
            v.x = pack_bf16x2(acc[j0][0],     acc[j0][1]);
            v.y = pack_bf16x2(acc[j0 + 1][0], acc[j0 + 1][1]);
            v.z = pack_bf16x2(acc[j0][2],     acc[j0][3]);
            v.w = pack_bf16x2(acc[j0 + 1][2], acc[j0 + 1][3]);
            *(uint4*)(Bb + (size_t)(BF16_OFF + ((kfg * 8 + half * 4 + mt) * 32 + lane) * 16)) = v;
        }
    }
}

// ---------------------------------------------------------------- GEMM
// 128x128 tile, 8 warps (4m x 2n), 2 CTA/SM, 5 K-stages of 32KB, ring of 3.
// One barrier per stage; prefetch right after it. All 6 LDS of a kf group
// issued back-to-back BEFORE its 16 MMAs (latency covered by MMA stream).
#define STAGE_BYTES 32768
#define SMEM_GEMM   (3 * STAGE_BYTES)

template <bool TF32>
__device__ __forceinline__ void compute_stage(uint32_t sA, uint32_t sB,
                                              int mw, int nw, int lane,
                                              float acc[2][8][4]) {
#pragma unroll
    for (int kf = 0; kf < 4; kf++) {
        uint32_t b[8][2];
        uint32_t a[2][4];
#pragma unroll
        for (int jp = 0; jp < 4; jp++) {
            uint32_t addr = sB + ((kf * 8 + nw * 4 + jp) * 32 + lane) * 16;
            asm volatile("ld.shared.v4.u32 {%0,%1,%2,%3}, [%4];"
                : "=r"(b[2 * jp][0]), "=r"(b[2 * jp][1]),
                  "=r"(b[2 * jp + 1][0]), "=r"(b[2 * jp + 1][1])
                : "r"(addr) : "memory");
        }
#pragma unroll
        for (int i = 0; i < 2; i++) {
            uint32_t addr = sA + ((kf * 8 + mw * 2 + i) * 32 + lane) * 16;
            asm volatile("ld.shared.v4.u32 {%0,%1,%2,%3}, [%4];"
                : "=r"(a[i][0]), "=r"(a[i][1]), "=r"(a[i][2]), "=r"(a[i][3])
                : "r"(addr) : "memory");
        }
#pragma unroll
        for (int i = 0; i < 2; i++) {
#pragma unroll
            for (int j = 0; j < 8; j++) {
                if (TF32)
                    asm volatile("mma.sync.aligned.m16n8k8.row.col.f32.tf32.tf32.f32 "
                        "{%0,%1,%2,%3}, {%4,%5,%6,%7}, {%8,%9}, {%0,%1,%2,%3};"
                        : "+f"(acc[i][j][0]), "+f"(acc[i][j][1]),
                          "+f"(acc[i][j][2]), "+f"(acc[i][j][3])
                        : "r"(a[i][0]), "r"(a[i][1]), "r"(a[i][2]), "r"(a[i][3]),
                          "r"(b[j][0]), "r"(b[j][1]));
                else
                    asm volatile("mma.sync.aligned.m16n8k16.row.col.f32.bf16.bf16.f32 "
                        "{%0,%1,%2,%3}, {%4,%5,%6,%7}, {%8,%9}, {%0,%1,%2,%3};"
                        : "+f"(acc[i][j][0]), "+f"(acc[i][j][1]),
                          "+f"(acc[i][j][2]), "+f"(acc[i][j][3])
                        : "r"(a[i][0]), "r"(a[i][1]), "r"(a[i][2]), "r"(a[i][3]),
                          "r"(b[j][0]), "r"(b[j][1]));
            }
        }
    }
}

__global__ void __launch_bounds__(256, 2) gemm_kernel(float* __restrict__ out) {
    extern __shared__ char smem[];
    const uint32_t sb = smem_u32(smem);
    const int tid  = threadIdx.x;
    const int lane = tid & 31;
    const int w    = tid >> 5;
    const int mw   = w & 3;
    const int nw   = w >> 2;

    const int bx = blockIdx.x, by = blockIdx.y, h = blockIdx.z;
    const unsigned char* Ab = g_Apk + (size_t)(h * 16 + by) * ABLOCK;
    const unsigned char* Bb = g_Bpk + (size_t)(h * 16 + bx) * ABLOCK;

    auto prefetch = [&](int s) {
        const int sl = s % 3;
        const size_t goff = (s < 4) ? (size_t)s * 16384 : (size_t)BF16_OFF;
        const uint32_t dA = sb + sl * STAGE_BYTES;
        const uint32_t dB = dA + 16384;
#pragma unroll
        for (int i = 0; i < 4; i++) {
            const int off = (tid + i * 256) * 16;
            cp_async16(dA + off, Ab + goff + off);
            cp_async16(dB + off, Bb + goff + off);
        }
        asm volatile("cp.async.commit_group;" ::: "memory");
    };

    float acc[2][8][4];
#pragma unroll
    for (int i = 0; i < 2; i++)
#pragma unroll
        for (int j = 0; j < 8; j++)
#pragma unroll
            for (int c = 0; c < 4; c++) acc[i][j][c] = 0.f;

    prefetch(0);
    prefetch(1);

#pragma unroll
    for (int s = 0; s < 5; s++) {
        if (s == 4) asm volatile("cp.async.wait_group 0;" ::: "memory");
        else        asm volatile("cp.async.wait_group 1;" ::: "memory");
        __syncthreads();   // also proves all warps finished stage s-1 reads
        if (s + 2 < 5) prefetch(s + 2);   // slot (s+2)%3 == (s-1)%3, now free
        const uint32_t sA = sb + (s % 3) * STAGE_BYTES;
        const uint32_t sB = sA + 16384;
        if (s < 4) compute_stage<true >(sA, sB, mw, nw, lane, acc);
        else       compute_stage<false>(sA, sB, mw, nw, lane, acc);
    }

    // epilogue: STG.64, full coalesced rows
    const int g = lane >> 2, tg = lane & 3;
    const size_t rowbase = (size_t)h * 2048;
#pragma unroll
    for (int i = 0; i < 2; i++) {
        const int m = by * 128 + mw * 32 + i * 16 + g;
        float* r0 = out + (rowbase + m)     * 2048 + bx * 128 + nw * 64;
        float* r1 = out + (rowbase + m + 8) * 2048 + bx * 128 + nw * 64;
#pragma unroll
        for (int j = 0; j < 8; j++) {
            *(float2*)(r0 + j * 8 + tg * 2) = make_float2(acc[i][j][0], acc[i][j][1]);
            *(float2*)(r1 + j * 8 + tg * 2) = make_float2(acc[i][j][2], acc[i][j][3]);
        }
    }
}

// ---------------------------------------------------------------- launch
extern "C" void kernel_launch(void* const* d_in, const int* in_sizes, int n_in,
                              void* d_out, int out_size) {
    const float* q  = (const float*)d_in[0];
    const float* ko = (const float*)d_in[1];
    const float* kq = (const float*)d_in[2];
    const float* G  = (const float*)d_in[3];
    float* out = (float*)d_out;

    cudaFuncSetAttribute(prep_ab, cudaFuncAttributeMaxDynamicSharedMemorySize, SMEM_PREP);
    cudaFuncSetAttribute(gemm_kernel, cudaFuncAttributeMaxDynamicSharedMemorySize, SMEM_GEMM);

    gsplit_kernel<<<16, 256>>>(G);
    prep_ab<<<dim3(NBLK64, 2), 256, SMEM_PREP>>>(
        (const float4*)q, (const float4*)ko, (const float4*)kq);

    dim3 grid(TROW / 128, NROW / 128, BH);
    gemm_kernel<<<grid, 256, SMEM_GEMM>>>(out);
}

// round 17
// speedup vs baseline: 1.1881x; 1.0332x over previous
#include <cuda_runtime.h>
#include <cuda_bf16.h>
#include <cstdint>

// ---------------------------------------------------------------- constants
#define BH        32
#define NROW      2048
#define TROW      2048
#define ROWS      (BH * 2048)        // 65536 rows per side
#define NBLK64    (ROWS / 64)        // 1024 blocks of 64 rows
#define NBLK128   (ROWS / 128)       // 512 blocks of 128 rows
#define ABLOCK    81920              // 64KB tf32 frags + 16KB bf16 frags
#define BF16_OFF  65536

// Packed operand buffers in MMA-fragment order (~40MB each)
__device__ __align__(128) unsigned char g_Apk[(size_t)NBLK128 * ABLOCK];
__device__ __align__(128) unsigned char g_Bpk[(size_t)NBLK128 * ABLOCK];
// G tf32 hi/lo in projection-B-fragment order: [kf 0..15][jj 0..7][lane] uint2
__device__ __align__(128) uint2 g_GFhi[4096];
__device__ __align__(128) uint2 g_GFlo[4096];

// ---------------------------------------------------------------- helpers
__device__ __forceinline__ uint32_t smem_u32(const void* p) {
    uint32_t a;
    asm("{ .reg .u64 t; cvta.to.shared.u64 t, %1; cvt.u32.u64 %0, t; }" : "=r"(a) : "l"(p));
    return a;
}
__device__ __forceinline__ uint32_t f2tf32(float v) {
    uint32_t o;
    asm("cvt.rna.tf32.f32 %0, %1;" : "=r"(o) : "f"(v));
    return o;
}
__device__ __forceinline__ uint32_t pack_bf16x2(float lo, float hi) {
    uint32_t o;   // first PTX source -> upper half
    asm("cvt.rn.bf16x2.f32 %0, %1, %2;" : "=r"(o) : "f"(hi), "f"(lo));
    return o;
}
__device__ __forceinline__ void cp_async16(uint32_t saddr, const void* gptr) {
    asm volatile("cp.async.cg.shared.global [%0], [%1], 16;"
                 :: "r"(saddr), "l"(__cvta_generic_to_global(gptr)) : "memory");
}
__device__ __forceinline__ float signf(float v) {
    return (v > 0.f) ? 1.f : ((v < 0.f) ? -1.f : 0.f);
}
__device__ __forceinline__ void mma_tf32_rr(float acc[4], const uint32_t a[4],
                                            uint32_t b0, uint32_t b1) {
    asm volatile("mma.sync.aligned.m16n8k8.row.col.f32.tf32.tf32.f32 "
        "{%0,%1,%2,%3}, {%4,%5,%6,%7}, {%8,%9}, {%0,%1,%2,%3};"
        : "+f"(acc[0]), "+f"(acc[1]), "+f"(acc[2]), "+f"(acc[3])
        : "r"(a[0]), "r"(a[1]), "r"(a[2]), "r"(a[3]), "r"(b0), "r"(b1));
}

// ---------------------------------------------------------------- G split
__global__ void gsplit_kernel(const float* __restrict__ G) {
    const int idx = blockIdx.x * 256 + threadIdx.x;   // 0..4095
    if (idx >= 4096) return;
    const int lane = idx & 31, jj = (idx >> 5) & 7, kf = idx >> 8;
    const int g = lane >> 2, tg = lane & 3;
    const int r = jj * 8 + g, k = kf * 8 + tg;
    const float g0 = G[k * 64 + r], g1 = G[(k + 4) * 64 + r];
    const uint32_t h0 = f2tf32(g0), h1 = f2tf32(g1);
    g_GFhi[idx] = make_uint2(h0, h1);
    g_GFlo[idx] = make_uint2(f2tf32(g0 - __uint_as_float(h0)),
                             f2tf32(g1 - __uint_as_float(h1)));
}

// ---------------------------------------------------------------- prep (merged)
// blockIdx.y == 0: A side (q). blockIdx.y == 1: B side (ko, kq).
// Fully warp-autonomous: each warp owns a private 16-row smem slab; no
// __syncthreads anywhere — only __syncwarp between per-warp phases.
#define RSTR  132
#define SLABF (16 * RSTR)                 // floats per slab
#define SMEM_PREP (8 * SLABF * 4)         // 67584 B -> 3 CTA/SM

__global__ void __launch_bounds__(256) prep_ab(const float4* __restrict__ q4,
                                               const float4* __restrict__ ko4,
                                               const float4* __restrict__ kq4) {
    extern __shared__ float sm[];

    const int tid = threadIdx.x;
    const int blk = blockIdx.x;
    const int side = blockIdx.y;
    const int half = blk & 1, blk128 = blk >> 1;

    const int lane = tid & 31, w = tid >> 5;
    const int g = lane >> 2, tg = lane & 3;
    const int mt = w & 3, nh = w >> 2;

    float* S = sm + w * SLABF;            // private slab [16][RSTR]
    // this warp's 16-row global slice (contiguous 8KB)
    const size_t gb4 = ((size_t)blk * 64 + mt * 16) * 32;

    if (side == 0) {
        unsigned char* Ab = g_Apk + (size_t)blk128 * ABLOCK;

        // load q slab (coalesced, warp-local)
#pragma unroll
        for (int it = 0; it < 16; it++)
            *(float4*)&S[it * RSTR + lane * 4] = q4[gb4 + it * 32 + lane];
        __syncwarp();

        float acc[4][4];
#pragma unroll
        for (int j = 0; j < 4; j++)
#pragma unroll
            for (int c = 0; c < 4; c++) acc[j][c] = 0.f;

#pragma unroll
        for (int kf = 0; kf < 16; kf++) {
            const int k0 = kf * 8 + tg;
            uint32_t a[4];
            a[0] = f2tf32(S[g * RSTR + k0]);
            a[1] = f2tf32(S[(g + 8) * RSTR + k0]);
            a[2] = f2tf32(S[g * RSTR + k0 + 4]);
            a[3] = f2tf32(S[(g + 8) * RSTR + k0 + 4]);
            if ((kf >> 3) == nh) {      // fused tf32 A-frag store
                uint4 v; v.x = a[0]; v.y = a[1]; v.z = a[2]; v.w = a[3];
                *(uint4*)(Ab + (size_t)((kf * 8 + half * 4 + mt) * 512 + lane * 16)) = v;
            }
#pragma unroll
            for (int j = 0; j < 4; j++) {
                const uint2 bh = __ldg(&g_GFhi[(kf * 8 + nh * 4 + j) * 32 + lane]);
                mma_tf32_rr(acc[j], a, bh.x, bh.y);
            }
        }

#pragma unroll
        for (int j = 0; j < 4; j++)
#pragma unroll
            for (int c = 0; c < 4; c++) acc[j][c] *= (1.0f / 64.0f);
#pragma unroll
        for (int kk = 0; kk < 2; kk++) {
            const int kfg = 2 * nh + kk, j0 = 2 * kk;
            uint4 v;
            v.x = pack_bf16x2(acc[j0][0],     acc[j0][1]);
            v.y = pack_bf16x2(acc[j0][2],     acc[j0][3]);
            v.z = pack_bf16x2(acc[j0 + 1][0], acc[j0 + 1][1]);
            v.w = pack_bf16x2(acc[j0 + 1][2], acc[j0 + 1][3]);
            *(uint4*)(Ab + (size_t)(BF16_OFF + (kfg * 8 + half * 4 + mt) * 512 + lane * 16)) = v;
        }
    } else {
        unsigned char* Bb = g_Bpk + (size_t)blk128 * ABLOCK;

        // phase 1: load kq slab
#pragma unroll
        for (int it = 0; it < 16; it++)
            *(float4*)&S[it * RSTR + lane * 4] = kq4[gb4 + it * 32 + lane];
        __syncwarp();

        // phase 2: pack tf32 B frag-pairs from kq
#pragma unroll
        for (int kk = 0; kk < 8; kk++) {
            const int kf = nh * 8 + kk;
            const int k0 = kf * 8 + tg;
            uint4 v;
            v.x = f2tf32(S[g * RSTR + k0]);
            v.y = f2tf32(S[g * RSTR + k0 + 4]);
            v.z = f2tf32(S[(g + 8) * RSTR + k0]);
            v.w = f2tf32(S[(g + 8) * RSTR + k0 + 4]);
            *(uint4*)(Bb + (size_t)(((kf * 8 + half * 4 + mt) * 32 + lane) * 16)) = v;
        }
        __syncwarp();

        // phase 3: residual in place: S := ko - S
#pragma unroll
        for (int it = 0; it < 16; it++) {
            const float4 a = ko4[gb4 + it * 32 + lane];
            float4* p = (float4*)&S[it * RSTR + lane * 4];
            const float4 b = *p;
            *p = make_float4(a.x - b.x, a.y - b.y, a.z - b.z, a.w - b.w);
        }
        __syncwarp();

        // phase 4: 3xTF32 projection MMA (sign path needs precision)
        float acc[4][4];
#pragma unroll
        for (int j = 0; j < 4; j++)
#pragma unroll
            for (int c = 0; c < 4; c++) acc[j][c] = 0.f;

#pragma unroll
        for (int kf = 0; kf < 16; kf++) {
            const int k0 = kf * 8 + tg;
            const float e0 = S[g * RSTR + k0];
            const float e1 = S[(g + 8) * RSTR + k0];
            const float e2 = S[g * RSTR + k0 + 4];
            const float e3 = S[(g + 8) * RSTR + k0 + 4];
            uint32_t ahi[4] = {f2tf32(e0), f2tf32(e1), f2tf32(e2), f2tf32(e3)};
            uint32_t alo[4];
            alo[0] = f2tf32(e0 - __uint_as_float(ahi[0]));
            alo[1] = f2tf32(e1 - __uint_as_float(ahi[1]));
            alo[2] = f2tf32(e2 - __uint_as_float(ahi[2]));
            alo[3] = f2tf32(e3 - __uint_as_float(ahi[3]));
#pragma unroll
            for (int j = 0; j < 4; j++) {
                const int gi = (kf * 8 + nh * 4 + j) * 32 + lane;
                const uint2 bh = __ldg(&g_GFhi[gi]);
                const uint2 bl = __ldg(&g_GFlo[gi]);
                mma_tf32_rr(acc[j], ahi, bh.x, bh.y);
                mma_tf32_rr(acc[j], ahi, bl.x, bl.y);
                mma_tf32_rr(acc[j], alo, bh.x, bh.y);
            }
        }

#pragma unroll
        for (int j = 0; j < 4; j++)
#pragma unroll
            for (int c = 0; c < 4; c++) acc[j][c] = signf(acc[j][c]);
#pragma unroll
        for (int kk = 0; kk < 2; kk++) {
            const int kfg = 2 * nh + kk, j0 = 2 * kk;
            uint4 v;
            v.x = pack_bf16x2(acc[j0][0],     acc[j0][1]);
            v.y = pack_bf16x2(acc[j0 + 1][0], acc[j0 + 1][1]);
            v.z = pack_bf16x2(acc[j0][2],     acc[j0][3]);
            v.w = pack_bf16x2(acc[j0 + 1][2], acc[j0 + 1][3]);
            *(uint4*)(Bb + (size_t)(BF16_OFF + ((kfg * 8 + half * 4 + mt) * 32 + lane) * 16)) = v;
        }
    }
}

// ---------------------------------------------------------------- GEMM
// 128x128 tile, 8 warps (4m x 2n), 2 CTA/SM, 5 K-stages of 32KB, ring of 3.
// One barrier per stage; prefetch right after it; kf-group LDS hoisted.
#define STAGE_BYTES 32768
#define SMEM_GEMM   (3 * STAGE_BYTES)

template <bool TF32>
__device__ __forceinline__ void compute_stage(uint32_t sA, uint32_t sB,
                                              int mw, int nw, int lane,
                                              float acc[2][8][4]) {
#pragma unroll
    for (int kf = 0; kf < 4; kf++) {
        uint32_t b[8][2];
        uint32_t a[2][4];
#pragma unroll
        for (int jp = 0; jp < 4; jp++) {
            uint32_t addr = sB + ((kf * 8 + nw * 4 + jp) * 32 + lane) * 16;
            asm volatile("ld.shared.v4.u32 {%0,%1,%2,%3}, [%4];"
                : "=r"(b[2 * jp][0]), "=r"(b[2 * jp][1]),
                  "=r"(b[2 * jp + 1][0]), "=r"(b[2 * jp + 1][1])
                : "r"(addr) : "memory");
        }
#pragma unroll
        for (int i = 0; i < 2; i++) {
            uint32_t addr = sA + ((kf * 8 + mw * 2 + i) * 32 + lane) * 16;
            asm volatile("ld.shared.v4.u32 {%0,%1,%2,%3}, [%4];"
                : "=r"(a[i][0]), "=r"(a[i][1]), "=r"(a[i][2]), "=r"(a[i][3])
                : "r"(addr) : "memory");
        }
#pragma unroll
        for (int i = 0; i < 2; i++) {
#pragma unroll
            for (int j = 0; j < 8; j++) {
                if (TF32)
                    asm volatile("mma.sync.aligned.m16n8k8.row.col.f32.tf32.tf32.f32 "
                        "{%0,%1,%2,%3}, {%4,%5,%6,%7}, {%8,%9}, {%0,%1,%2,%3};"
                        : "+f"(acc[i][j][0]), "+f"(acc[i][j][1]),
                          "+f"(acc[i][j][2]), "+f"(acc[i][j][3])
                        : "r"(a[i][0]), "r"(a[i][1]), "r"(a[i][2]), "r"(a[i][3]),
                          "r"(b[j][0]), "r"(b[j][1]));
                else
                    asm volatile("mma.sync.aligned.m16n8k16.row.col.f32.bf16.bf16.f32 "
                        "{%0,%1,%2,%3}, {%4,%5,%6,%7}, {%8,%9}, {%0,%1,%2,%3};"
                        : "+f"(acc[i][j][0]), "+f"(acc[i][j][1]),
                          "+f"(acc[i][j][2]), "+f"(acc[i][j][3])
                        : "r"(a[i][0]), "r"(a[i][1]), "r"(a[i][2]), "r"(a[i][3]),
                          "r"(b[j][0]), "r"(b[j][1]));
            }
        }
    }
}

__global__ void __launch_bounds__(256, 2) gemm_kernel(float* __restrict__ out) {
    extern __shared__ char smem[];
    const uint32_t sb = smem_u32(smem);
    const int tid  = threadIdx.x;
    const int lane = tid & 31;
    const int w    = tid >> 5;
    const int mw   = w & 3;
    const int nw   = w >> 2;

    const int bx = blockIdx.x, by = blockIdx.y, h = blockIdx.z;
    const unsigned char* Ab = g_Apk + (size_t)(h * 16 + by) * ABLOCK;
    const unsigned char* Bb = g_Bpk + (size_t)(h * 16 + bx) * ABLOCK;

    auto prefetch = [&](int s) {
        const int sl = s % 3;
        const size_t goff = (s < 4) ? (size_t)s * 16384 : (size_t)BF16_OFF;
        const uint32_t dA = sb + sl * STAGE_BYTES;
        const uint32_t dB = dA + 16384;
#pragma unroll
        for (int i = 0; i < 4; i++) {
            const int off = (tid + i * 256) * 16;
            cp_async16(dA + off, Ab + goff + off);
            cp_async16(dB + off, Bb + goff + off);
        }
        asm volatile("cp.async.commit_group;" ::: "memory");
    };

    float acc[2][8][4];
#pragma unroll
    for (int i = 0; i < 2; i++)
#pragma unroll
        for (int j = 0; j < 8; j++)
#pragma unroll
            for (int c = 0; c < 4; c++) acc[i][j][c] = 0.f;

    prefetch(0);
    prefetch(1);

#pragma unroll
    for (int s = 0; s < 5; s++) {
        if (s == 4) asm volatile("cp.async.wait_group 0;" ::: "memory");
        else        asm volatile("cp.async.wait_group 1;" ::: "memory");
        __syncthreads();   // also proves all warps finished stage s-1 reads
        if (s + 2 < 5) prefetch(s + 2);   // slot (s+2)%3 == (s-1)%3, now free
        const uint32_t sA = sb + (s % 3) * STAGE_BYTES;
        const uint32_t sB = sA + 16384;
        if (s < 4) compute_stage<true >(sA, sB, mw, nw, lane, acc);
        else       compute_stage<false>(sA, sB, mw, nw, lane, acc);
    }

    // epilogue: STG.64, full coalesced rows
    const int g = lane >> 2, tg = lane & 3;
    const size_t rowbase = (size_t)h * 2048;
#pragma unroll
    for (int i = 0; i < 2; i++) {
        const int m = by * 128 + mw * 32 + i * 16 + g;
        float* r0 = out + (rowbase + m)     * 2048 + bx * 128 + nw * 64;
        float* r1 = out + (rowbase + m + 8) * 2048 + bx * 128 + nw * 64;
#pragma unroll
        for (int j = 0; j < 8; j++) {
            *(float2*)(r0 + j * 8 + tg * 2) = make_float2(acc[i][j][0], acc[i][j][1]);
            *(float2*)(r1 + j * 8 + tg * 2) = make_float2(acc[i][j][2], acc[i][j][3]);
        }
    }
}

// ---------------------------------------------------------------- launch
extern "C" void kernel_launch(void* const* d_in, const int* in_sizes, int n_in,
                              void* d_out, int out_size) {
    const float* q  = (const float*)d_in[0];
    const float* ko = (const float*)d_in[1];
    const float* kq = (const float*)d_in[2];
    const float* G  = (const float*)d_in[3];
    float* out = (float*)d_out;

    cudaFuncSetAttribute(prep_ab, cudaFuncAttributeMaxDynamicSharedMemorySize, SMEM_PREP);
    cudaFuncSetAttribute(gemm_kernel, cudaFuncAttributeMaxDynamicSharedMemorySize, SMEM_GEMM);

    gsplit_kernel<<<16, 256>>>(G);
    prep_ab<<<dim3(NBLK64, 2), 256, SMEM_PREP>>>(
        (const float4*)q, (const float4*)ko, (const float4*)kq);

    dim3 grid(TROW / 128, NROW / 128, BH);
    gemm_kernel<<<grid, 256, SMEM_GEMM>>>(out);
}